// round 9
// baseline (speedup 1.0000x reference)
#include <cuda_runtime.h>
#include <math.h>

#define N_NODES   100000
#define N_EDGES   1600000
#define D         128
#define N_GRAPHS  128
#define N_CLASSES 10

typedef unsigned long long ull;

// packed dual-FMA: acc(2xf32) += a(2xf32) * b(2xf32)
#define FMA2(acc, a, b) \
    asm("fma.rn.f32x2 %0, %1, %2, %0;" : "+l"(acc) : "l"(a), "l"(b))

// ---------------- scratch (static device globals; no allocs) ----------------
__device__ __align__(16) float g_h  [(size_t)N_NODES * D];   // ping buffer
__device__ __align__(16) float g_buf[(size_t)N_NODES * D];   // pong buffer
__device__ __align__(16) float g_wt [3][D * D];              // transposed weights
__device__ float g_dinv[N_NODES];
__device__ int   g_degi[N_NODES];
__device__ int   g_off [N_NODES + 1];
__device__ int   g_cur [N_NODES];
__device__ __align__(8) int2 g_csr[N_EDGES];                 // {src, norm bits}
__device__ __align__(16) float g_sums[N_GRAPHS * D];
__device__ int   g_end [N_GRAPHS];
__device__ int   g_bsum[391];
__device__ int   g_bpre[391];

// ---------------- setup ----------------
__global__ void zero_kernel() {
    int i = blockIdx.x * blockDim.x + threadIdx.x;
    if (i < N_NODES)      g_degi[i] = 0;
    if (i < N_GRAPHS * D) g_sums[i] = 0.0f;
}

__global__ void hist_kernel(const int* __restrict__ dst) {
    int e = blockIdx.x * blockDim.x + threadIdx.x;
    if (e < N_EDGES) atomicAdd(&g_degi[dst[e]], 1);
}

__global__ void dinv_kernel() {
    int i = blockIdx.x * blockDim.x + threadIdx.x;
    if (i < N_NODES) g_dinv[i] = rsqrtf((float)g_degi[i] + 1.0f);
}

// ---- 3-phase parallel scan over g_degi -> g_off / g_cur ----
__global__ void blockred_kernel() {           // grid 391 x 256
    __shared__ int sh[256];
    int t = threadIdx.x;
    int i = blockIdx.x * 256 + t;
    sh[t] = (i < N_NODES) ? g_degi[i] : 0;
    __syncthreads();
    for (int ofs = 128; ofs > 0; ofs >>= 1) {
        if (t < ofs) sh[t] += sh[t + ofs];
        __syncthreads();
    }
    if (t == 0) g_bsum[blockIdx.x] = sh[0];
}

__global__ void bscan_kernel() {              // 1 block x 512
    __shared__ int sh[512];
    int t = threadIdx.x;
    int v = (t < 391) ? g_bsum[t] : 0;
    sh[t] = v;
    __syncthreads();
    for (int ofs = 1; ofs < 512; ofs <<= 1) {
        int u = (t >= ofs) ? sh[t - ofs] : 0;
        __syncthreads();
        sh[t] += u;
        __syncthreads();
    }
    if (t < 391) g_bpre[t] = sh[t] - v;       // exclusive prefix of block sums
    if (t == 0) g_off[N_NODES] = N_EDGES;
}

__global__ void blockscan_kernel() {          // grid 391 x 256
    __shared__ int sh[256];
    int t = threadIdx.x;
    int i = blockIdx.x * 256 + t;
    int v = (i < N_NODES) ? g_degi[i] : 0;
    sh[t] = v;
    __syncthreads();
    for (int ofs = 1; ofs < 256; ofs <<= 1) {
        int u = (t >= ofs) ? sh[t - ofs] : 0;
        __syncthreads();
        sh[t] += u;
        __syncthreads();
    }
    if (i < N_NODES) {
        int excl = sh[t] - v + g_bpre[blockIdx.x];
        g_off[i] = excl;
        g_cur[i] = excl;
    }
}

__global__ void place_kernel(const int* __restrict__ ei) {
    int e = blockIdx.x * blockDim.x + threadIdx.x;
    if (e >= N_EDGES) return;
    int s = ei[e];
    int d = ei[N_EDGES + e];
    int pos = atomicAdd(&g_cur[d], 1);
    float nrm = g_dinv[s] * g_dinv[d];
    g_csr[pos] = make_int2(s, __float_as_int(nrm));
}

// batch is sorted: cumulative end index per graph (no atomics)
__global__ void boundary_kernel(const int* __restrict__ batch) {
    int i = blockIdx.x * blockDim.x + threadIdx.x;
    if (i >= N_NODES) return;
    int b  = batch[i];
    int bn = (i + 1 < N_NODES) ? batch[i + 1] : N_GRAPHS;
    for (int g = b; g < bn; g++) g_end[g] = i + 1;
    if (i == 0)
        for (int g = 0; g < b; g++) g_end[g] = 0;
}

// ---------------- W transpose: WT[c][k] = W[k][c] ----------------
__global__ void transpose_kernel(const float* __restrict__ W,
                                 float* __restrict__ WT) {
    __shared__ float tile[32][33];
    int bx = (blockIdx.x & 3) * 32;            // k tile
    int by = (blockIdx.x >> 2) * 32;           // c tile
    int tx = threadIdx.x & 31, ty = threadIdx.x >> 5;  // 32x8
    for (int r = 0; r < 32; r += 8)
        tile[ty + r][tx] = W[(bx + ty + r) * D + by + tx];
    __syncthreads();
    for (int r = 0; r < 32; r += 8)
        WT[(by + ty + r) * D + bx + tx] = tile[tx][ty + r];
}

// ---------------- GEMM: H = X @ W, W given transposed (WT[c][k]) ----------
// f32x2 packed FMA paired along K: both operands load pre-packed, zero packs.
__global__ void gemm_kernel(const float* __restrict__ X,
                            const float* __restrict__ WT,
                            float* __restrict__ H) {
    int block_row = blockIdx.x * 32;
    int lane = threadIdx.x & 31;               // cols 4*lane..4*lane+3
    int rt   = threadIdx.x >> 5;               // rows rt + 8*j

    ull acc2[4][4];                            // [j][c] (even-k, odd-k) partials
#pragma unroll
    for (int j = 0; j < 4; j++)
#pragma unroll
        for (int c = 0; c < 4; c++) acc2[j][c] = 0ULL;

    for (int k = 0; k < D; k += 4) {
        ulonglong2 wb[4];
#pragma unroll
        for (int c = 0; c < 4; c++)
            wb[c] = *(const ulonglong2*)&WT[(lane * 4 + c) * D + k];
#pragma unroll
        for (int j = 0; j < 4; j++) {
            int r = block_row + rt + 8 * j;
            ulonglong2 xa = *(const ulonglong2*)&X[(size_t)r * D + k];
#pragma unroll
            for (int c = 0; c < 4; c++) {
                FMA2(acc2[j][c], xa.x, wb[c].x);
                FMA2(acc2[j][c], xa.y, wb[c].y);
            }
        }
    }
#pragma unroll
    for (int j = 0; j < 4; j++) {
        float o[4];
#pragma unroll
        for (int c = 0; c < 4; c++) {
            unsigned lo, hi;
            asm("mov.b64 {%0,%1}, %2;" : "=r"(lo), "=r"(hi) : "l"(acc2[j][c]));
            o[c] = __uint_as_float(lo) + __uint_as_float(hi);
        }
        int r = block_row + rt + 8 * j;
        *(float4*)&H[(size_t)r * D + lane * 4] =
            make_float4(o[0], o[1], o[2], o[3]);
    }
}

// ---------------- fused gather: out = [relu]( dinv^2*h + sum csr + b ) ----
__device__ __forceinline__ float4 f4fma(float4 a, float n, float4 v) {
    a.x += n * v.x; a.y += n * v.y; a.z += n * v.z; a.w += n * v.w;
    return a;
}

__global__ void gather_kernel(const float* __restrict__ H,
                              const float* __restrict__ b,
                              float* __restrict__ out, int relu) {
    int node = (blockIdx.x * blockDim.x + threadIdx.x) >> 5;
    if (node >= N_NODES) return;
    int lane = threadIdx.x & 31;

    float di = g_dinv[node];
    float s  = di * di;
    float4 acc = ((const float4*)(H + (size_t)node * D))[lane];
    acc.x *= s; acc.y *= s; acc.z *= s; acc.w *= s;

    int beg = g_off[node], end = g_off[node + 1];
    int j = beg;
    for (; j + 4 <= end; j += 4) {             // 4-wide: independent load chains
        int2 e0 = g_csr[j + 0], e1 = g_csr[j + 1];
        int2 e2 = g_csr[j + 2], e3 = g_csr[j + 3];
        float4 v0 = ((const float4*)(H + (size_t)e0.x * D))[lane];
        float4 v1 = ((const float4*)(H + (size_t)e1.x * D))[lane];
        float4 v2 = ((const float4*)(H + (size_t)e2.x * D))[lane];
        float4 v3 = ((const float4*)(H + (size_t)e3.x * D))[lane];
        acc = f4fma(acc, __int_as_float(e0.y), v0);
        acc = f4fma(acc, __int_as_float(e1.y), v1);
        acc = f4fma(acc, __int_as_float(e2.y), v2);
        acc = f4fma(acc, __int_as_float(e3.y), v3);
    }
    for (; j < end; j++) {
        int2 e = g_csr[j];
        float4 v = ((const float4*)(H + (size_t)e.x * D))[lane];
        acc = f4fma(acc, __int_as_float(e.y), v);
    }

    float4 bb = ((const float4*)b)[lane];
    acc.x += bb.x; acc.y += bb.y; acc.z += bb.z; acc.w += bb.w;
    if (relu) {
        acc.x = fmaxf(acc.x, 0.0f); acc.y = fmaxf(acc.y, 0.0f);
        acc.z = fmaxf(acc.z, 0.0f); acc.w = fmaxf(acc.w, 0.0f);
    }
    ((float4*)(out + (size_t)node * D))[lane] = acc;
}

// last layer: same gather, pooled straight into g_sums
__global__ void gather_pool_kernel(const float* __restrict__ H,
                                   const float* __restrict__ b,
                                   const int* __restrict__ batch) {
    int node = (blockIdx.x * blockDim.x + threadIdx.x) >> 5;
    if (node >= N_NODES) return;
    int lane = threadIdx.x & 31;

    float di = g_dinv[node];
    float s  = di * di;
    float4 acc = ((const float4*)(H + (size_t)node * D))[lane];
    acc.x *= s; acc.y *= s; acc.z *= s; acc.w *= s;

    int beg = g_off[node], end = g_off[node + 1];
    int j = beg;
    for (; j + 4 <= end; j += 4) {
        int2 e0 = g_csr[j + 0], e1 = g_csr[j + 1];
        int2 e2 = g_csr[j + 2], e3 = g_csr[j + 3];
        float4 v0 = ((const float4*)(H + (size_t)e0.x * D))[lane];
        float4 v1 = ((const float4*)(H + (size_t)e1.x * D))[lane];
        float4 v2 = ((const float4*)(H + (size_t)e2.x * D))[lane];
        float4 v3 = ((const float4*)(H + (size_t)e3.x * D))[lane];
        acc = f4fma(acc, __int_as_float(e0.y), v0);
        acc = f4fma(acc, __int_as_float(e1.y), v1);
        acc = f4fma(acc, __int_as_float(e2.y), v2);
        acc = f4fma(acc, __int_as_float(e3.y), v3);
    }
    for (; j < end; j++) {
        int2 e = g_csr[j];
        float4 v = ((const float4*)(H + (size_t)e.x * D))[lane];
        acc = f4fma(acc, __int_as_float(e.y), v);
    }

    float4 bb = ((const float4*)b)[lane];
    acc.x += bb.x; acc.y += bb.y; acc.z += bb.z; acc.w += bb.w;

    int g = batch[node];
    float* p = &g_sums[g * D + lane * 4];
    atomicAdd(p + 0, acc.x);
    atomicAdd(p + 1, acc.y);
    atomicAdd(p + 2, acc.z);
    atomicAdd(p + 3, acc.w);
}

// ---------------- head: mean-pool -> linear -> softmax --------------------
__global__ void head_kernel(const float* __restrict__ lin_W,
                            const float* __restrict__ lin_b,
                            float* __restrict__ out) {
    int g = threadIdx.x;
    if (g >= N_GRAPHS) return;
    int cnt = g_end[g] - (g > 0 ? g_end[g - 1] : 0);
    float inv = 1.0f / fmaxf((float)cnt, 1.0f);
    float logits[N_CLASSES];
#pragma unroll
    for (int j = 0; j < N_CLASSES; j++) logits[j] = lin_b[j];
    for (int c = 0; c < D; c++) {
        float p = g_sums[g * D + c] * inv;
#pragma unroll
        for (int j = 0; j < N_CLASSES; j++)
            logits[j] += p * lin_W[c * N_CLASSES + j];
    }
    float m = logits[0];
#pragma unroll
    for (int j = 1; j < N_CLASSES; j++) m = fmaxf(m, logits[j]);
    float ssum = 0.0f;
#pragma unroll
    for (int j = 0; j < N_CLASSES; j++) {
        logits[j] = expf(logits[j] - m);
        ssum += logits[j];
    }
    float isum = 1.0f / ssum;
#pragma unroll
    for (int j = 0; j < N_CLASSES; j++)
        out[g * N_CLASSES + j] = logits[j] * isum;
}

// ---------------- launch ----------------
extern "C" void kernel_launch(void* const* d_in, const int* in_sizes, int n_in,
                              void* d_out, int out_size) {
    const float* x     = (const float*)d_in[0];
    const int*   ei    = (const int*)d_in[1];    // int32 (JAX x64 disabled)
    const int*   batch = (const int*)d_in[2];
    const float* W0    = (const float*)d_in[3];
    const float* b0    = (const float*)d_in[4];
    const float* W1    = (const float*)d_in[5];
    const float* b1    = (const float*)d_in[6];
    const float* W2    = (const float*)d_in[7];
    const float* b2    = (const float*)d_in[8];
    const float* lW    = (const float*)d_in[9];
    const float* lb    = (const float*)d_in[10];
    float* out = (float*)d_out;

    void *ph, *pb, *pw;
    cudaGetSymbolAddress(&ph, g_h);
    cudaGetSymbolAddress(&pb, g_buf);
    cudaGetSymbolAddress(&pw, g_wt);
    float* H  = (float*)ph;
    float* B  = (float*)pb;
    float* WT = (float*)pw;

    const int NT = 256;
    const int node_blocks = (N_NODES + NT - 1) / NT;   // 391
    const int edge_blocks = (N_EDGES + NT - 1) / NT;
    const int gemm_blocks = N_NODES / 32;              // 3125
    const int gath_blocks = N_NODES / 8;               // warp/node, 8/block

    // CSR build + bookkeeping (all graph-capturable, deterministic)
    zero_kernel<<<node_blocks, NT>>>();
    hist_kernel<<<edge_blocks, NT>>>(ei + N_EDGES);
    dinv_kernel<<<node_blocks, NT>>>();
    blockred_kernel<<<node_blocks, NT>>>();
    bscan_kernel<<<1, 512>>>();
    blockscan_kernel<<<node_blocks, NT>>>();
    place_kernel<<<edge_blocks, NT>>>(ei);
    boundary_kernel<<<node_blocks, NT>>>(batch);

    // weight transposes (tiny)
    transpose_kernel<<<16, 256>>>(W0, WT + 0 * D * D);
    transpose_kernel<<<16, 256>>>(W1, WT + 1 * D * D);
    transpose_kernel<<<16, 256>>>(W2, WT + 2 * D * D);

    // layer 0: x -> H -> B
    gemm_kernel<<<gemm_blocks, NT>>>(x, WT + 0 * D * D, H);
    gather_kernel<<<gath_blocks, NT>>>(H, b0, B, 1);

    // layer 1: B -> H -> B
    gemm_kernel<<<gemm_blocks, NT>>>(B, WT + 1 * D * D, H);
    gather_kernel<<<gath_blocks, NT>>>(H, b1, B, 1);

    // layer 2: B -> H -> pooled sums
    gemm_kernel<<<gemm_blocks, NT>>>(B, WT + 2 * D * D, H);
    gather_pool_kernel<<<gath_blocks, NT>>>(H, b2, batch);

    head_kernel<<<1, 128>>>(lW, lb, out);
}

// round 10
// speedup vs baseline: 1.7855x; 1.7855x over previous
#include <cuda_runtime.h>
#include <math.h>

#define N_NODES   100000
#define N_EDGES   1600000
#define D         128
#define N_GRAPHS  128
#define N_CLASSES 10

typedef unsigned long long ull;

// packed dual-FMA: acc(2xf32) += a(2xf32) * b(2xf32)
#define FMA2(acc, a, b) \
    asm("fma.rn.f32x2 %0, %1, %2, %0;" : "+l"(acc) : "l"(a), "l"(b))

// ---------------- scratch (static device globals; no allocs) ----------------
__device__ __align__(16) float g_h  [(size_t)N_NODES * D];   // ping buffer
__device__ __align__(16) float g_buf[(size_t)N_NODES * D];   // pong buffer
__device__ __align__(16) float g_wp [3][D * D];              // k-pair-packed weights
__device__ float g_dinv[N_NODES];
__device__ int   g_degi[N_NODES];
__device__ int   g_off [N_NODES + 1];
__device__ int   g_cur [N_NODES];
__device__ __align__(8) int2 g_csr[N_EDGES];                 // {src, norm bits}
__device__ __align__(16) float g_sums[N_GRAPHS * D];
__device__ int   g_end [N_GRAPHS];
__device__ int   g_bsum[391];
__device__ int   g_bpre[391];

// ---------------- setup ----------------
__global__ void zero_kernel() {
    int i = blockIdx.x * blockDim.x + threadIdx.x;
    if (i < N_NODES)      g_degi[i] = 0;
    if (i < N_GRAPHS * D) g_sums[i] = 0.0f;
}

__global__ void hist_kernel(const int* __restrict__ dst) {
    int e = blockIdx.x * blockDim.x + threadIdx.x;
    if (e < N_EDGES) atomicAdd(&g_degi[dst[e]], 1);
}

__global__ void dinv_kernel() {
    int i = blockIdx.x * blockDim.x + threadIdx.x;
    if (i < N_NODES) g_dinv[i] = rsqrtf((float)g_degi[i] + 1.0f);
}

// ---- 3-phase parallel scan over g_degi -> g_off / g_cur ----
__global__ void blockred_kernel() {           // grid 391 x 256
    __shared__ int sh[256];
    int t = threadIdx.x;
    int i = blockIdx.x * 256 + t;
    sh[t] = (i < N_NODES) ? g_degi[i] : 0;
    __syncthreads();
    for (int ofs = 128; ofs > 0; ofs >>= 1) {
        if (t < ofs) sh[t] += sh[t + ofs];
        __syncthreads();
    }
    if (t == 0) g_bsum[blockIdx.x] = sh[0];
}

__global__ void bscan_kernel() {              // 1 block x 512
    __shared__ int sh[512];
    int t = threadIdx.x;
    int v = (t < 391) ? g_bsum[t] : 0;
    sh[t] = v;
    __syncthreads();
    for (int ofs = 1; ofs < 512; ofs <<= 1) {
        int u = (t >= ofs) ? sh[t - ofs] : 0;
        __syncthreads();
        sh[t] += u;
        __syncthreads();
    }
    if (t < 391) g_bpre[t] = sh[t] - v;       // exclusive prefix of block sums
    if (t == 0) g_off[N_NODES] = N_EDGES;
}

__global__ void blockscan_kernel() {          // grid 391 x 256
    __shared__ int sh[256];
    int t = threadIdx.x;
    int i = blockIdx.x * 256 + t;
    int v = (i < N_NODES) ? g_degi[i] : 0;
    sh[t] = v;
    __syncthreads();
    for (int ofs = 1; ofs < 256; ofs <<= 1) {
        int u = (t >= ofs) ? sh[t - ofs] : 0;
        __syncthreads();
        sh[t] += u;
        __syncthreads();
    }
    if (i < N_NODES) {
        int excl = sh[t] - v + g_bpre[blockIdx.x];
        g_off[i] = excl;
        g_cur[i] = excl;
    }
}

__global__ void place_kernel(const int* __restrict__ ei) {
    int e = blockIdx.x * blockDim.x + threadIdx.x;
    if (e >= N_EDGES) return;
    int s = ei[e];
    int d = ei[N_EDGES + e];
    int pos = atomicAdd(&g_cur[d], 1);
    float nrm = g_dinv[s] * g_dinv[d];
    g_csr[pos] = make_int2(s, __float_as_int(nrm));
}

// batch is sorted: cumulative end index per graph (no atomics)
__global__ void boundary_kernel(const int* __restrict__ batch) {
    int i = blockIdx.x * blockDim.x + threadIdx.x;
    if (i >= N_NODES) return;
    int b  = batch[i];
    int bn = (i + 1 < N_NODES) ? batch[i + 1] : N_GRAPHS;
    for (int g = b; g < bn; g++) g_end[g] = i + 1;
    if (i == 0)
        for (int g = 0; g < b; g++) g_end[g] = 0;
}

// ---------------- W pack: WP[(k/2)*2D + c*2 + (k&1)] = W[k][c] ------------
// For each k-pair, consecutive columns' (w_k, w_k+1) 64-bit pairs contiguous.
__global__ void pack_kernel(const float* __restrict__ W,
                            float* __restrict__ WP) {
    int i = blockIdx.x * blockDim.x + threadIdx.x;   // over D*D
    if (i >= D * D) return;
    int k = i >> 7, c = i & 127;
    WP[(k >> 1) * (2 * D) + c * 2 + (k & 1)] = W[i];
}

// ---------------- GEMM: H = X @ W (WP = packed W) -------------------------
// 256 thr/block, 32 rows/block. lane owns cols 4*lane..+3, rows rt + 8*j.
// FMA2 pairs along K; both operands arrive pre-packed, fully coalesced.
__global__ void gemm_kernel(const float* __restrict__ X,
                            const float* __restrict__ WP,
                            float* __restrict__ H) {
    int block_row = blockIdx.x * 32;
    int lane = threadIdx.x & 31;
    int rt   = threadIdx.x >> 5;

    ull acc2[4][4];                            // [j][c]: (even-k, odd-k) partials
#pragma unroll
    for (int j = 0; j < 4; j++)
#pragma unroll
        for (int c = 0; c < 4; c++) acc2[j][c] = 0ULL;

    for (int k = 0; k < D; k += 4) {           // 2 k-pairs per chunk
        // WP row for k-pair kp: 2D floats; thread's 4 cols = 4 ull = 2 float4
        ulonglong2 w0 = *(const ulonglong2*)&WP[(k >> 1) * (2 * D) + lane * 8];
        ulonglong2 w0b = *(const ulonglong2*)&WP[(k >> 1) * (2 * D) + lane * 8 + 4];
        ulonglong2 w1 = *(const ulonglong2*)&WP[((k >> 1) + 1) * (2 * D) + lane * 8];
        ulonglong2 w1b = *(const ulonglong2*)&WP[((k >> 1) + 1) * (2 * D) + lane * 8 + 4];
#pragma unroll
        for (int j = 0; j < 4; j++) {
            int r = block_row + rt + 8 * j;
            ulonglong2 xa = *(const ulonglong2*)&X[(size_t)r * D + k];
            // k-pair 0: xa.x = (x_k, x_k+1)
            FMA2(acc2[j][0], xa.x, w0.x);
            FMA2(acc2[j][1], xa.x, w0.y);
            FMA2(acc2[j][2], xa.x, w0b.x);
            FMA2(acc2[j][3], xa.x, w0b.y);
            // k-pair 1: xa.y = (x_k+2, x_k+3)
            FMA2(acc2[j][0], xa.y, w1.x);
            FMA2(acc2[j][1], xa.y, w1.y);
            FMA2(acc2[j][2], xa.y, w1b.x);
            FMA2(acc2[j][3], xa.y, w1b.y);
        }
    }
#pragma unroll
    for (int j = 0; j < 4; j++) {
        float o[4];
#pragma unroll
        for (int c = 0; c < 4; c++) {
            unsigned lo, hi;
            asm("mov.b64 {%0,%1}, %2;" : "=r"(lo), "=r"(hi) : "l"(acc2[j][c]));
            o[c] = __uint_as_float(lo) + __uint_as_float(hi);
        }
        int r = block_row + rt + 8 * j;
        *(float4*)&H[(size_t)r * D + lane * 4] =
            make_float4(o[0], o[1], o[2], o[3]);
    }
}

// ---------------- fused gather: out = [relu]( dinv^2*h + sum csr + b ) ----
__device__ __forceinline__ float4 f4fma(float4 a, float n, float4 v) {
    a.x += n * v.x; a.y += n * v.y; a.z += n * v.z; a.w += n * v.w;
    return a;
}

__global__ void gather_kernel(const float* __restrict__ H,
                              const float* __restrict__ b,
                              float* __restrict__ out, int relu) {
    int node = (blockIdx.x * blockDim.x + threadIdx.x) >> 5;
    if (node >= N_NODES) return;
    int lane = threadIdx.x & 31;

    float di = g_dinv[node];
    float s  = di * di;
    float4 acc = ((const float4*)(H + (size_t)node * D))[lane];
    acc.x *= s; acc.y *= s; acc.z *= s; acc.w *= s;

    int beg = g_off[node], end = g_off[node + 1];
    int j = beg;
    for (; j + 4 <= end; j += 4) {             // 4-wide: independent load chains
        int2 e0 = g_csr[j + 0], e1 = g_csr[j + 1];
        int2 e2 = g_csr[j + 2], e3 = g_csr[j + 3];
        float4 v0 = ((const float4*)(H + (size_t)e0.x * D))[lane];
        float4 v1 = ((const float4*)(H + (size_t)e1.x * D))[lane];
        float4 v2 = ((const float4*)(H + (size_t)e2.x * D))[lane];
        float4 v3 = ((const float4*)(H + (size_t)e3.x * D))[lane];
        acc = f4fma(acc, __int_as_float(e0.y), v0);
        acc = f4fma(acc, __int_as_float(e1.y), v1);
        acc = f4fma(acc, __int_as_float(e2.y), v2);
        acc = f4fma(acc, __int_as_float(e3.y), v3);
    }
    for (; j < end; j++) {
        int2 e = g_csr[j];
        float4 v = ((const float4*)(H + (size_t)e.x * D))[lane];
        acc = f4fma(acc, __int_as_float(e.y), v);
    }

    float4 bb = ((const float4*)b)[lane];
    acc.x += bb.x; acc.y += bb.y; acc.z += bb.z; acc.w += bb.w;
    if (relu) {
        acc.x = fmaxf(acc.x, 0.0f); acc.y = fmaxf(acc.y, 0.0f);
        acc.z = fmaxf(acc.z, 0.0f); acc.w = fmaxf(acc.w, 0.0f);
    }
    ((float4*)(out + (size_t)node * D))[lane] = acc;
}

// last layer: same gather, pooled straight into g_sums
__global__ void gather_pool_kernel(const float* __restrict__ H,
                                   const float* __restrict__ b,
                                   const int* __restrict__ batch) {
    int node = (blockIdx.x * blockDim.x + threadIdx.x) >> 5;
    if (node >= N_NODES) return;
    int lane = threadIdx.x & 31;

    float di = g_dinv[node];
    float s  = di * di;
    float4 acc = ((const float4*)(H + (size_t)node * D))[lane];
    acc.x *= s; acc.y *= s; acc.z *= s; acc.w *= s;

    int beg = g_off[node], end = g_off[node + 1];
    int j = beg;
    for (; j + 4 <= end; j += 4) {
        int2 e0 = g_csr[j + 0], e1 = g_csr[j + 1];
        int2 e2 = g_csr[j + 2], e3 = g_csr[j + 3];
        float4 v0 = ((const float4*)(H + (size_t)e0.x * D))[lane];
        float4 v1 = ((const float4*)(H + (size_t)e1.x * D))[lane];
        float4 v2 = ((const float4*)(H + (size_t)e2.x * D))[lane];
        float4 v3 = ((const float4*)(H + (size_t)e3.x * D))[lane];
        acc = f4fma(acc, __int_as_float(e0.y), v0);
        acc = f4fma(acc, __int_as_float(e1.y), v1);
        acc = f4fma(acc, __int_as_float(e2.y), v2);
        acc = f4fma(acc, __int_as_float(e3.y), v3);
    }
    for (; j < end; j++) {
        int2 e = g_csr[j];
        float4 v = ((const float4*)(H + (size_t)e.x * D))[lane];
        acc = f4fma(acc, __int_as_float(e.y), v);
    }

    float4 bb = ((const float4*)b)[lane];
    acc.x += bb.x; acc.y += bb.y; acc.z += bb.z; acc.w += bb.w;

    int g = batch[node];
    float* p = &g_sums[g * D + lane * 4];
    atomicAdd(p + 0, acc.x);
    atomicAdd(p + 1, acc.y);
    atomicAdd(p + 2, acc.z);
    atomicAdd(p + 3, acc.w);
}

// ---------------- head: mean-pool -> linear -> softmax --------------------
__global__ void head_kernel(const float* __restrict__ lin_W,
                            const float* __restrict__ lin_b,
                            float* __restrict__ out) {
    int g = threadIdx.x;
    if (g >= N_GRAPHS) return;
    int cnt = g_end[g] - (g > 0 ? g_end[g - 1] : 0);
    float inv = 1.0f / fmaxf((float)cnt, 1.0f);
    float logits[N_CLASSES];
#pragma unroll
    for (int j = 0; j < N_CLASSES; j++) logits[j] = lin_b[j];
    for (int c = 0; c < D; c++) {
        float p = g_sums[g * D + c] * inv;
#pragma unroll
        for (int j = 0; j < N_CLASSES; j++)
            logits[j] += p * lin_W[c * N_CLASSES + j];
    }
    float m = logits[0];
#pragma unroll
    for (int j = 1; j < N_CLASSES; j++) m = fmaxf(m, logits[j]);
    float ssum = 0.0f;
#pragma unroll
    for (int j = 0; j < N_CLASSES; j++) {
        logits[j] = expf(logits[j] - m);
        ssum += logits[j];
    }
    float isum = 1.0f / ssum;
#pragma unroll
    for (int j = 0; j < N_CLASSES; j++)
        out[g * N_CLASSES + j] = logits[j] * isum;
}

// ---------------- launch ----------------
extern "C" void kernel_launch(void* const* d_in, const int* in_sizes, int n_in,
                              void* d_out, int out_size) {
    const float* x     = (const float*)d_in[0];
    const int*   ei    = (const int*)d_in[1];    // int32 (JAX x64 disabled)
    const int*   batch = (const int*)d_in[2];
    const float* W0    = (const float*)d_in[3];
    const float* b0    = (const float*)d_in[4];
    const float* W1    = (const float*)d_in[5];
    const float* b1    = (const float*)d_in[6];
    const float* W2    = (const float*)d_in[7];
    const float* b2    = (const float*)d_in[8];
    const float* lW    = (const float*)d_in[9];
    const float* lb    = (const float*)d_in[10];
    float* out = (float*)d_out;

    void *ph, *pb, *pw;
    cudaGetSymbolAddress(&ph, g_h);
    cudaGetSymbolAddress(&pb, g_buf);
    cudaGetSymbolAddress(&pw, g_wp);
    float* H  = (float*)ph;
    float* B  = (float*)pb;
    float* WP = (float*)pw;

    const int NT = 256;
    const int node_blocks = (N_NODES + NT - 1) / NT;   // 391
    const int edge_blocks = (N_EDGES + NT - 1) / NT;
    const int gemm_blocks = N_NODES / 32;              // 3125
    const int gath_blocks = N_NODES / 8;               // warp/node, 8/block
    const int pack_blocks = (D * D + NT - 1) / NT;     // 64

    // CSR build + bookkeeping (all graph-capturable, deterministic)
    zero_kernel<<<node_blocks, NT>>>();
    hist_kernel<<<edge_blocks, NT>>>(ei + N_EDGES);
    dinv_kernel<<<node_blocks, NT>>>();
    blockred_kernel<<<node_blocks, NT>>>();
    bscan_kernel<<<1, 512>>>();
    blockscan_kernel<<<node_blocks, NT>>>();
    place_kernel<<<edge_blocks, NT>>>(ei);
    boundary_kernel<<<node_blocks, NT>>>(batch);

    // weight packing (tiny)
    pack_kernel<<<pack_blocks, NT>>>(W0, WP + 0 * D * D);
    pack_kernel<<<pack_blocks, NT>>>(W1, WP + 1 * D * D);
    pack_kernel<<<pack_blocks, NT>>>(W2, WP + 2 * D * D);

    // layer 0: x -> H -> B
    gemm_kernel<<<gemm_blocks, NT>>>(x, WP + 0 * D * D, H);
    gather_kernel<<<gath_blocks, NT>>>(H, b0, B, 1);

    // layer 1: B -> H -> B
    gemm_kernel<<<gemm_blocks, NT>>>(B, WP + 1 * D * D, H);
    gather_kernel<<<gath_blocks, NT>>>(H, b1, B, 1);

    // layer 2: B -> H -> pooled sums
    gemm_kernel<<<gemm_blocks, NT>>>(B, WP + 2 * D * D, H);
    gather_pool_kernel<<<gath_blocks, NT>>>(H, b2, batch);

    head_kernel<<<1, 128>>>(lW, lb, out);
}

// round 11
// speedup vs baseline: 2.1053x; 1.1791x over previous
#include <cuda_runtime.h>
#include <math.h>

#define N_NODES   100000
#define N_EDGES   1600000
#define D         128
#define N_GRAPHS  128
#define N_CLASSES 10

typedef unsigned long long ull;

// packed dual-FMA: acc(2xf32) += a(2xf32) * b(2xf32)
#define FMA2(acc, a, b) \
    asm("fma.rn.f32x2 %0, %1, %2, %0;" : "+l"(acc) : "l"(a), "l"(b))

// ---------------- scratch (static device globals; no allocs) ----------------
__device__ __align__(16) float g_h  [(size_t)N_NODES * D];   // ping buffer
__device__ __align__(16) float g_buf[(size_t)N_NODES * D];   // pong buffer
__device__ __align__(16) float g_wp [2][D * D];              // k-pair-packed W0,W1
__device__ float g_dinv[N_NODES];
__device__ int   g_degi[N_NODES];
__device__ int   g_off [N_NODES + 1];
__device__ int   g_cur [N_NODES];
__device__ __align__(8) int2 g_csr[N_EDGES];                 // {src, norm bits}
__device__ __align__(16) float g_sums[N_GRAPHS * D];
__device__ int   g_end [N_GRAPHS];
__device__ int   g_bsum[391];
__device__ int   g_bpre[391];

// ---------------- setup ----------------
__global__ void zero_kernel() {
    int i = blockIdx.x * blockDim.x + threadIdx.x;
    if (i < N_NODES)      g_degi[i] = 0;
    if (i < N_GRAPHS * D) g_sums[i] = 0.0f;
}

__global__ void hist_kernel(const int* __restrict__ dst) {
    int e = blockIdx.x * blockDim.x + threadIdx.x;
    if (e < N_EDGES) atomicAdd(&g_degi[dst[e]], 1);
}

__global__ void dinv_kernel() {
    int i = blockIdx.x * blockDim.x + threadIdx.x;
    if (i < N_NODES) g_dinv[i] = rsqrtf((float)g_degi[i] + 1.0f);
}

// ---- 3-phase parallel scan over g_degi -> g_off / g_cur ----
__global__ void blockred_kernel() {           // grid 391 x 256
    __shared__ int sh[256];
    int t = threadIdx.x;
    int i = blockIdx.x * 256 + t;
    sh[t] = (i < N_NODES) ? g_degi[i] : 0;
    __syncthreads();
    for (int ofs = 128; ofs > 0; ofs >>= 1) {
        if (t < ofs) sh[t] += sh[t + ofs];
        __syncthreads();
    }
    if (t == 0) g_bsum[blockIdx.x] = sh[0];
}

__global__ void bscan_kernel() {              // 1 block x 512
    __shared__ int sh[512];
    int t = threadIdx.x;
    int v = (t < 391) ? g_bsum[t] : 0;
    sh[t] = v;
    __syncthreads();
    for (int ofs = 1; ofs < 512; ofs <<= 1) {
        int u = (t >= ofs) ? sh[t - ofs] : 0;
        __syncthreads();
        sh[t] += u;
        __syncthreads();
    }
    if (t < 391) g_bpre[t] = sh[t] - v;       // exclusive prefix of block sums
    if (t == 0) g_off[N_NODES] = N_EDGES;
}

__global__ void blockscan_kernel() {          // grid 391 x 256
    __shared__ int sh[256];
    int t = threadIdx.x;
    int i = blockIdx.x * 256 + t;
    int v = (i < N_NODES) ? g_degi[i] : 0;
    sh[t] = v;
    __syncthreads();
    for (int ofs = 1; ofs < 256; ofs <<= 1) {
        int u = (t >= ofs) ? sh[t - ofs] : 0;
        __syncthreads();
        sh[t] += u;
        __syncthreads();
    }
    if (i < N_NODES) {
        int excl = sh[t] - v + g_bpre[blockIdx.x];
        g_off[i] = excl;
        g_cur[i] = excl;
    }
}

__global__ void place_kernel(const int* __restrict__ ei) {
    int e = blockIdx.x * blockDim.x + threadIdx.x;
    if (e >= N_EDGES) return;
    int s = ei[e];
    int d = ei[N_EDGES + e];
    int pos = atomicAdd(&g_cur[d], 1);
    float nrm = g_dinv[s] * g_dinv[d];
    g_csr[pos] = make_int2(s, __float_as_int(nrm));
}

// batch is sorted: cumulative end index per graph (no atomics)
__global__ void boundary_kernel(const int* __restrict__ batch) {
    int i = blockIdx.x * blockDim.x + threadIdx.x;
    if (i >= N_NODES) return;
    int b  = batch[i];
    int bn = (i + 1 < N_NODES) ? batch[i + 1] : N_GRAPHS;
    for (int g = b; g < bn; g++) g_end[g] = i + 1;
    if (i == 0)
        for (int g = 0; g < b; g++) g_end[g] = 0;
}

// ---------------- W pack: WP[(k/2)*2D + c*2 + (k&1)] = W[k][c] ------------
__global__ void pack_kernel(const float* __restrict__ W,
                            float* __restrict__ WP) {
    int i = blockIdx.x * blockDim.x + threadIdx.x;   // over D*D
    if (i >= D * D) return;
    int k = i >> 7, c = i & 127;
    WP[(k >> 1) * (2 * D) + c * 2 + (k & 1)] = W[i];
}

// ---------------- GEMM+bias+relu: Y = relu(X @ W + b) ---------------------
// 256 thr/block, 32 rows/block. lane owns cols 4*lane..+3, rows rt + 8*j.
// FMA2 pairs along K; WP pre-packed, fully coalesced.
__global__ void gemm_br_kernel(const float* __restrict__ X,
                               const float* __restrict__ WP,
                               const float* __restrict__ b,
                               float* __restrict__ Y) {
    int block_row = blockIdx.x * 32;
    int lane = threadIdx.x & 31;
    int rt   = threadIdx.x >> 5;

    ull acc2[4][4];                            // [j][c]: (even-k, odd-k) partials
#pragma unroll
    for (int j = 0; j < 4; j++)
#pragma unroll
        for (int c = 0; c < 4; c++) acc2[j][c] = 0ULL;

    for (int k = 0; k < D; k += 4) {           // 2 k-pairs per chunk
        ulonglong2 w0  = *(const ulonglong2*)&WP[(k >> 1) * (2 * D) + lane * 8];
        ulonglong2 w0b = *(const ulonglong2*)&WP[(k >> 1) * (2 * D) + lane * 8 + 4];
        ulonglong2 w1  = *(const ulonglong2*)&WP[((k >> 1) + 1) * (2 * D) + lane * 8];
        ulonglong2 w1b = *(const ulonglong2*)&WP[((k >> 1) + 1) * (2 * D) + lane * 8 + 4];
#pragma unroll
        for (int j = 0; j < 4; j++) {
            int r = block_row + rt + 8 * j;
            ulonglong2 xa = *(const ulonglong2*)&X[(size_t)r * D + k];
            FMA2(acc2[j][0], xa.x, w0.x);
            FMA2(acc2[j][1], xa.x, w0.y);
            FMA2(acc2[j][2], xa.x, w0b.x);
            FMA2(acc2[j][3], xa.x, w0b.y);
            FMA2(acc2[j][0], xa.y, w1.x);
            FMA2(acc2[j][1], xa.y, w1.y);
            FMA2(acc2[j][2], xa.y, w1b.x);
            FMA2(acc2[j][3], xa.y, w1b.y);
        }
    }
    float4 bb = ((const float4*)b)[lane];
    float bv[4] = {bb.x, bb.y, bb.z, bb.w};
#pragma unroll
    for (int j = 0; j < 4; j++) {
        float o[4];
#pragma unroll
        for (int c = 0; c < 4; c++) {
            unsigned lo, hi;
            asm("mov.b64 {%0,%1}, %2;" : "=r"(lo), "=r"(hi) : "l"(acc2[j][c]));
            o[c] = fmaxf(__uint_as_float(lo) + __uint_as_float(hi) + bv[c], 0.0f);
        }
        int r = block_row + rt + 8 * j;
        *(float4*)&Y[(size_t)r * D + lane * 4] =
            make_float4(o[0], o[1], o[2], o[3]);
    }
}

// ---------------- pure gather: out = dinv^2*x_node + sum norm*x_src ------
__device__ __forceinline__ float4 f4fma(float4 a, float n, float4 v) {
    a.x += n * v.x; a.y += n * v.y; a.z += n * v.z; a.w += n * v.w;
    return a;
}

__device__ __forceinline__ float4 gather_body(const float* __restrict__ X,
                                              int node, int lane) {
    float di = g_dinv[node];
    float s  = di * di;
    float4 acc = ((const float4*)(X + (size_t)node * D))[lane];
    acc.x *= s; acc.y *= s; acc.z *= s; acc.w *= s;

    int beg = g_off[node], end = g_off[node + 1];
    int j = beg;
    for (; j + 8 <= end; j += 8) {             // 8-wide independent load chains
        int2 e0 = g_csr[j + 0], e1 = g_csr[j + 1];
        int2 e2 = g_csr[j + 2], e3 = g_csr[j + 3];
        int2 e4 = g_csr[j + 4], e5 = g_csr[j + 5];
        int2 e6 = g_csr[j + 6], e7 = g_csr[j + 7];
        float4 v0 = ((const float4*)(X + (size_t)e0.x * D))[lane];
        float4 v1 = ((const float4*)(X + (size_t)e1.x * D))[lane];
        float4 v2 = ((const float4*)(X + (size_t)e2.x * D))[lane];
        float4 v3 = ((const float4*)(X + (size_t)e3.x * D))[lane];
        float4 v4 = ((const float4*)(X + (size_t)e4.x * D))[lane];
        float4 v5 = ((const float4*)(X + (size_t)e5.x * D))[lane];
        float4 v6 = ((const float4*)(X + (size_t)e6.x * D))[lane];
        float4 v7 = ((const float4*)(X + (size_t)e7.x * D))[lane];
        acc = f4fma(acc, __int_as_float(e0.y), v0);
        acc = f4fma(acc, __int_as_float(e1.y), v1);
        acc = f4fma(acc, __int_as_float(e2.y), v2);
        acc = f4fma(acc, __int_as_float(e3.y), v3);
        acc = f4fma(acc, __int_as_float(e4.y), v4);
        acc = f4fma(acc, __int_as_float(e5.y), v5);
        acc = f4fma(acc, __int_as_float(e6.y), v6);
        acc = f4fma(acc, __int_as_float(e7.y), v7);
    }
    for (; j + 2 <= end; j += 2) {
        int2 e0 = g_csr[j + 0], e1 = g_csr[j + 1];
        float4 v0 = ((const float4*)(X + (size_t)e0.x * D))[lane];
        float4 v1 = ((const float4*)(X + (size_t)e1.x * D))[lane];
        acc = f4fma(acc, __int_as_float(e0.y), v0);
        acc = f4fma(acc, __int_as_float(e1.y), v1);
    }
    if (j < end) {
        int2 e = g_csr[j];
        float4 v = ((const float4*)(X + (size_t)e.x * D))[lane];
        acc = f4fma(acc, __int_as_float(e.y), v);
    }
    return acc;
}

__global__ void gather_kernel(const float* __restrict__ X,
                              float* __restrict__ out) {
    int node = (blockIdx.x * blockDim.x + threadIdx.x) >> 5;
    if (node >= N_NODES) return;
    int lane = threadIdx.x & 31;
    float4 acc = gather_body(X, node, lane);
    ((float4*)(out + (size_t)node * D))[lane] = acc;
}

// last layer: gather on PRE-GEMM features, pooled into g_sums (linearity:
// sum_g agg(Y W2) = (sum_g agg(Y)) W2, applied in head)
__global__ void gather_pool_kernel(const float* __restrict__ X,
                                   const int* __restrict__ batch) {
    int node = (blockIdx.x * blockDim.x + threadIdx.x) >> 5;
    if (node >= N_NODES) return;
    int lane = threadIdx.x & 31;
    float4 acc = gather_body(X, node, lane);
    int g = batch[node];
    float* p = &g_sums[g * D + lane * 4];
    atomicAdd(p + 0, acc.x);
    atomicAdd(p + 1, acc.y);
    atomicAdd(p + 2, acc.z);
    atomicAdd(p + 3, acc.w);
}

// ---------------- head: S·W2/cnt + b2 -> linear -> softmax ----------------
// block per graph, 128 threads (thread = output channel c)
__global__ void head_kernel(const float* __restrict__ W2,
                            const float* __restrict__ b2,
                            const float* __restrict__ lin_W,
                            const float* __restrict__ lin_b,
                            float* __restrict__ out) {
    __shared__ float sp[D];
    __shared__ float sl[N_CLASSES];
    int g = blockIdx.x;
    int c = threadIdx.x;
    int cnt = g_end[g] - (g > 0 ? g_end[g - 1] : 0);
    float inv = 1.0f / fmaxf((float)cnt, 1.0f);

    float acc = 0.0f;
    for (int k = 0; k < D; k++)
        acc += g_sums[g * D + k] * W2[k * D + c];
    sp[c] = acc * inv + b2[c];
    __syncthreads();

    if (c < N_CLASSES) {
        float l = lin_b[c];
        for (int k = 0; k < D; k++)
            l += sp[k] * lin_W[k * N_CLASSES + c];
        sl[c] = l;
    }
    __syncthreads();

    if (c == 0) {
        float m = sl[0];
#pragma unroll
        for (int j = 1; j < N_CLASSES; j++) m = fmaxf(m, sl[j]);
        float e[N_CLASSES], ssum = 0.0f;
#pragma unroll
        for (int j = 0; j < N_CLASSES; j++) { e[j] = expf(sl[j] - m); ssum += e[j]; }
        float isum = 1.0f / ssum;
#pragma unroll
        for (int j = 0; j < N_CLASSES; j++)
            out[g * N_CLASSES + j] = e[j] * isum;
    }
}

// ---------------- launch ----------------
extern "C" void kernel_launch(void* const* d_in, const int* in_sizes, int n_in,
                              void* d_out, int out_size) {
    const float* x     = (const float*)d_in[0];
    const int*   ei    = (const int*)d_in[1];    // int32 (JAX x64 disabled)
    const int*   batch = (const int*)d_in[2];
    const float* W0    = (const float*)d_in[3];
    const float* b0    = (const float*)d_in[4];
    const float* W1    = (const float*)d_in[5];
    const float* b1    = (const float*)d_in[6];
    const float* W2    = (const float*)d_in[7];
    const float* b2    = (const float*)d_in[8];
    const float* lW    = (const float*)d_in[9];
    const float* lb    = (const float*)d_in[10];
    float* out = (float*)d_out;

    void *ph, *pb, *pw;
    cudaGetSymbolAddress(&ph, g_h);
    cudaGetSymbolAddress(&pb, g_buf);
    cudaGetSymbolAddress(&pw, g_wp);
    float* H  = (float*)ph;
    float* B  = (float*)pb;
    float* WP = (float*)pw;

    const int NT = 256;
    const int node_blocks = (N_NODES + NT - 1) / NT;   // 391
    const int edge_blocks = (N_EDGES + NT - 1) / NT;
    const int gemm_blocks = N_NODES / 32;              // 3125
    const int gath_blocks = N_NODES / 8;               // warp/node, 8/block
    const int pack_blocks = (D * D + NT - 1) / NT;     // 64

    // CSR build + bookkeeping (graph-capturable, deterministic)
    zero_kernel<<<node_blocks, NT>>>();
    hist_kernel<<<edge_blocks, NT>>>(ei + N_EDGES);
    dinv_kernel<<<node_blocks, NT>>>();
    blockred_kernel<<<node_blocks, NT>>>();
    bscan_kernel<<<1, 512>>>();
    blockscan_kernel<<<node_blocks, NT>>>();
    place_kernel<<<edge_blocks, NT>>>(ei);
    boundary_kernel<<<node_blocks, NT>>>(batch);

    // weight packing (W0, W1 only; W2 applied in head)
    pack_kernel<<<pack_blocks, NT>>>(W0, WP + 0 * D * D);
    pack_kernel<<<pack_blocks, NT>>>(W1, WP + 1 * D * D);

    // layer 0: A0 = agg(x); Y0 = relu(A0 W0 + b0)
    gather_kernel<<<gath_blocks, NT>>>(x, H);
    gemm_br_kernel<<<gemm_blocks, NT>>>(H, WP + 0 * D * D, b0, B);

    // layer 1: A1 = agg(Y0); Y1 = relu(A1 W1 + b1)
    gather_kernel<<<gath_blocks, NT>>>(B, H);
    gemm_br_kernel<<<gemm_blocks, NT>>>(H, WP + 1 * D * D, b1, B);

    // layer 2 (projection folded into head): S = pool(agg(Y1))
    gather_pool_kernel<<<gath_blocks, NT>>>(B, batch);

    head_kernel<<<N_GRAPHS, D>>>(W2, b2, lW, lb, out);
}